// round 12
// baseline (speedup 1.0000x reference)
#include <cuda_runtime.h>

// B=8192, D=512, NUM_CLASSES=90, K=8
// Numerics (validated R9-R11): per dot, NEON VF4xIC2 structure:
//   8 independent serial FMA chains, chain j covers elements 8i+j (i=0..63);
//   combine v_e = fadd(chain_e, chain_{e+4}); dot = fadd(fadd(v0,v1),fadd(v2,v3));
//   d = fadd(1,dot). Epilogue f32 per-op rounded, k ascending. Batch sums double.
// R12: barrier-free main loop. c in SMEM (staged once), x straight from GMEM
// (coalescer dedup across the 8 k-lanes), d gathered via shfl, epilogue in-warp.

#define NUM_CLASSES 90
#define CHUNKS      4
#define CHUNK_B     2048
#define NBLK        (NUM_CLASSES * CHUNKS)   // 360
#define THREADS     256
#define NWARPS      8
#define CPAD        516    // 516 mod 32 = 4: each bank-group hit exactly 2x -> optimal

__device__ double   g_partials[NBLK];
__device__ unsigned g_count = 0;

__global__ __launch_bounds__(THREADS) void loss_main(
    const float* __restrict__ x,
    const float* __restrict__ centers,
    const int* __restrict__ labels,
    float* __restrict__ out)
{
    __shared__ float    cs[8 * CPAD];
    __shared__ int      list[CHUNK_B];
    __shared__ unsigned gmask[64];
    __shared__ int      gbase[64];
    __shared__ int      s_n;
    __shared__ double   red[NWARPS];
    __shared__ int      s_last;

    const int tid    = threadIdx.x;
    const int cls    = blockIdx.x / CHUNKS;
    const int chunk  = blockIdx.x % CHUNKS;
    const int base_b = chunk * CHUNK_B;
    const int warp   = tid >> 5;
    const int lane   = tid & 31;

    // ---- stage this class's 8 center rows into padded SMEM ----
    const float4* __restrict__ gc4 =
        reinterpret_cast<const float4*>(centers + (size_t)cls * 8 * 512);
    for (int u = tid; u < 1024; u += THREADS) {
        int row = u >> 7, f4 = u & 127;
        float4 v = gc4[row * 128 + f4];
        *reinterpret_cast<float4*>(&cs[row * CPAD + f4 * 4]) = v;
    }

    // ---- deterministic scan: samples in this 2048-chunk with label==cls ----
#pragma unroll
    for (int q = 0; q < 8; ++q) {
        int g = warp * 8 + q;
        int idx = base_b + g * 32 + lane;
        unsigned bal = __ballot_sync(0xFFFFFFFFu, labels[idx] == cls);
        if (lane == 0) gmask[g] = bal;
    }
    __syncthreads();
    if (tid == 0) {                 // serial prefix over 64 group counts
        int run = 0;
        for (int g = 0; g < 64; ++g) { gbase[g] = run; run += __popc(gmask[g]); }
        s_n = run;
    }
    __syncthreads();
#pragma unroll
    for (int q = 0; q < 8; ++q) {
        int g = warp * 8 + q;
        unsigned m = gmask[g];
        if ((m >> lane) & 1u)
            list[gbase[g] + __popc(m & ((1u << lane) - 1u))] = g * 32 + lane;
    }
    __syncthreads();

    const int n = s_n;

    // lane roles: group = which of 2 samples in this warp; (k,h) within 16 lanes
    const int group = lane >> 4;          // 0 or 1
    const int k     = (lane >> 1) & 7;    // 0..7
    const int h     = lane & 1;           // 0: chains 8i+0..3, 1: chains 8i+4..7
    const int gbase_lane = lane & 16;     // leader lane of my 16-lane sample group

    const float* cb = &cs[k * CPAD + h * 4];
    double bsum = 0.0;

    // ---- barrier-free main loop: warp w owns samples w*2+group, stride 16 ----
    for (int si0 = warp * 2; si0 < n; si0 += 2 * NWARPS) {
        const int si     = si0 + group;
        const bool active = (si < n);
        const int b = base_b + list[active ? si : (n - 1)];   // safe addr if idle

        const float4* __restrict__ xg =
            reinterpret_cast<const float4*>(x + (size_t)b * 512);

        // serial packet chain (exact validated order); x from GMEM, c from SMEM
        float4 acc = make_float4(0.f, 0.f, 0.f, 0.f);
#pragma unroll 8
        for (int i = 0; i < 64; ++i) {
            float4 xv = xg[2 * i + h];     // same 16B across the 8 k-lanes -> dedup
            float4 cv = *reinterpret_cast<const float4*>(cb + i * 8);
            acc.x = fmaf(xv.x, cv.x, acc.x);
            acc.y = fmaf(xv.y, cv.y, acc.y);
            acc.z = fmaf(xv.z, cv.z, acc.z);
            acc.w = fmaf(xv.w, cv.w, acc.w);
        }
        // combine partner chains (h^1); fadd is bitwise-commutative
        float px = __shfl_xor_sync(0xFFFFFFFFu, acc.x, 1);
        float py = __shfl_xor_sync(0xFFFFFFFFu, acc.y, 1);
        float pz = __shfl_xor_sync(0xFFFFFFFFu, acc.z, 1);
        float pw = __shfl_xor_sync(0xFFFFFFFFu, acc.w, 1);
        float v0 = __fadd_rn(acc.x, px);
        float v1 = __fadd_rn(acc.y, py);
        float v2 = __fadd_rn(acc.z, pz);
        float v3 = __fadd_rn(acc.w, pw);
        float dot = __fadd_rn(__fadd_rn(v0, v1), __fadd_rn(v2, v3));
        float d = __fadd_rn(1.0f, dot);   // all 16 lanes of the group hold d(k)

        // gather the 8 d_k of my sample via shfl (even lanes of my group)
        float dl[8];
#pragma unroll
        for (int j = 0; j < 8; ++j)
            dl[j] = __shfl_sync(0xFFFFFFFFu, d, gbase_lane + 2 * j);

        // per-op-rounded f32 epilogue, k ascending (identical to validated order)
        float s1 = dl[0];
#pragma unroll
        for (int j = 1; j < 8; ++j) s1 = __fadd_rn(s1, dl[j]);
        float accw = 0.f;
#pragma unroll
        for (int j = 0; j < 8; ++j) {
            float w = __fdiv_rn(dl[j], s1);
            float p = __fmul_rn(w, dl[j]);
            accw = __fadd_rn(accw, p);
        }
        if (active && (lane & 15) == 0)   // one lane per sample contributes
            bsum += (double)accw;
    }

    // ---- deterministic block reduction (double) ----
#pragma unroll
    for (int m = 16; m >= 1; m >>= 1)
        bsum += __shfl_xor_sync(0xFFFFFFFFu, bsum, m);
    if (lane == 0) red[warp] = bsum;
    __syncthreads();
    if (tid == 0) {
        double t = 0.0;
#pragma unroll
        for (int j = 0; j < NWARPS; ++j) t += red[j];
        g_partials[blockIdx.x] = t;
        __threadfence();
        unsigned old = atomicInc(&g_count, NBLK - 1);   // wraps -> auto reset
        s_last = (old == NBLK - 1);
    }
    __syncthreads();

    // ---- last block folds all partials (fixed order -> deterministic) ----
    if (s_last) {
        double v = 0.0;
        for (int i = tid; i < NBLK; i += THREADS)
            v += __ldcg(&g_partials[i]);
#pragma unroll
        for (int m = 16; m >= 1; m >>= 1)
            v += __shfl_xor_sync(0xFFFFFFFFu, v, m);
        if (lane == 0) red[warp] = v;
        __syncthreads();
        if (tid == 0) {
            double t = 0.0;
#pragma unroll
            for (int j = 0; j < NWARPS; ++j) t += red[j];
            out[0] = (float)(t * (1.0 / 8192.0));
        }
    }
}

extern "C" void kernel_launch(void* const* d_in, const int* in_sizes, int n_in,
                              void* d_out, int out_size)
{
    const float* x       = (const float*)d_in[0];
    const float* centers = (const float*)d_in[1];
    const int*   labels  = (const int*)d_in[2];
    float*       out     = (float*)d_out;

    loss_main<<<NBLK, THREADS>>>(x, centers, labels, out);
}